// round 16
// baseline (speedup 1.0000x reference)
#include <cuda_runtime.h>
#include <cuda_fp16.h>
#include <cstdint>
#include <math.h>

#define BATCH 8
#define SEQ   2048
#define EMBED 1024
#define BS    (BATCH * SEQ)          // 16384

// ---------------------------------------------------------------------------
// Device-global scratch (allocation-free rule) — all fp16 operands
// ---------------------------------------------------------------------------
__device__ __half g_xh[(size_t)BS * EMBED];
__device__ __half g_Wq[EMBED * EMBED];
__device__ __half g_Wk[EMBED * EMBED];
__device__ __half g_Wv[EMBED * EMBED];
__device__ __half g_Qh[(size_t)BS * EMBED];
__device__ __half g_Kh[(size_t)BS * EMBED];
__device__ __half g_Vth[(size_t)EMBED * BS];        // V pre-transposed [EMBED][BS]
__device__ __half g_SP[(size_t)BATCH * SEQ * SEQ];  // exp(scores), unnormalized
__device__ float  g_rowsum[BS];                     // per-row sums of exp(scores)

// ---------------------------------------------------------------------------
// Helpers
// ---------------------------------------------------------------------------
__device__ __forceinline__ uint32_t smem_u32(const void* p) {
    uint32_t a;
    asm("{ .reg .u64 t; cvta.to.shared.u64 t, %1; cvt.u32.u64 %0, t; }" : "=r"(a) : "l"(p));
    return a;
}

#define CP_ASYNC16(sm, gp) \
    asm volatile("cp.async.cg.shared.global [%0], [%1], 16;" :: "r"(sm), "l"(gp) : "memory")
#define CP_COMMIT()  asm volatile("cp.async.commit_group;" ::: "memory")
#define CP_WAITN(n)  asm volatile("cp.async.wait_group %0;" :: "n"(n) : "memory")

__device__ __forceinline__ void ldsm_x4(uint32_t* r, uint32_t addr) {
    asm volatile("ldmatrix.sync.aligned.m8n8.x4.shared.b16 {%0,%1,%2,%3}, [%4];"
                 : "=r"(r[0]), "=r"(r[1]), "=r"(r[2]), "=r"(r[3]) : "r"(addr));
}

__device__ __forceinline__ void mma16816(float* c, const uint32_t* a, const uint32_t* b) {
    asm volatile(
        "mma.sync.aligned.m16n8k16.row.col.f32.f16.f16.f32 "
        "{%0,%1,%2,%3}, {%4,%5,%6,%7}, {%8,%9}, {%0,%1,%2,%3};"
        : "+f"(c[0]), "+f"(c[1]), "+f"(c[2]), "+f"(c[3])
        : "r"(a[0]), "r"(a[1]), "r"(a[2]), "r"(a[3]), "r"(b[0]), "r"(b[1]));
}

// byte offset of 16B chunk (row, c) inside a [rows][64 fp16] tile, xor-swizzled
__device__ __forceinline__ uint32_t swz(int row, int c) {
    return (uint32_t)((row * 8 + (c ^ (row & 7))) * 16);
}

__device__ __forceinline__ uint32_t pack_half2(float v0, float v1) {
    __half h0 = __float2half(v0), h1 = __float2half(v1);
    return (uint32_t)__half_as_ushort(h0) | ((uint32_t)__half_as_ushort(h1) << 16);
}

// ---------------------------------------------------------------------------
// HMMA GEMM NT: C[M,N] = A[M,K] * B[N,K]^T, fp16 in, fp32 accum.
// CTA tile 128xNT (NT = 128 or 64), 256 threads = 8 warps (2x4),
// warp tile 64x(NT/4). K-chunk 64, 3-stage cp.async pipeline, 2 CTAs/SM.
// MODE 3: v=exp(acc) -> fp16 Ch (z-strided) + per-row sum atomics -> rowsum
// MODE 4: v=acc * (1/rowsum[row]) -> fp32 Cf (z-strided)          [PV]
// MODE 5: fused QKV:
//   z=0: v=(acc+bq[col])*qscale -> Qh ; z=1: v=acc+bk[col] -> Kh
//   z=2: A=Wv, B=xh, tile remap, v=acc+bv[row] -> Vth (ldc=BS)
// ---------------------------------------------------------------------------
#define NSTAGE 3
#define NTHR 256

template <int MODE, int NT>
__global__ void __launch_bounds__(NTHR, 2)
gemm_tc(const __half* __restrict__ Ah,
        const __half* B, const float* bias, float scale,
        float* __restrict__ Cf, __half* Ch,
        int lda, int ldb, int ldc, int nchunk,
        long long strideA, long long strideB, long long strideC,
        const __half* B2, const float* bias2, float scale2, __half* Ch2,
        const __half* A3, const __half* B3, const float* bias3, __half* Ch3,
        float* __restrict__ rowsum)
{
    constexpr int NG  = NT / 64;               // B ldsm groups per warp (>=1)
    constexpr int NTL = NT / 32;               // 8-col mma subtiles per warp
    constexpr int STG_BYTES = 16384 + NT * 128;
    constexpr int B_OFF = 16384;

    extern __shared__ char smem[];
    const uint32_t sbase = smem_u32(smem);
    const int tid = threadIdx.x;
    const int wid = tid >> 5;
    const int lane = tid & 31;
    const int wm = wid & 1;          // 0..1  M direction (64 rows each)
    const int wn = wid >> 1;         // 0..3  N direction (NT/4 cols each)

    const long long z = blockIdx.z;
    int rowA0 = blockIdx.y * 128;
    int colB0 = blockIdx.x * NT;

    if (MODE == 5) {
        if (z == 1) { B = B2; bias = bias2; scale = scale2; Ch = Ch2; }
        else if (z == 2) {
            // Vt: A=Wv[1024,1024], B=xh[16384,1024], out Vth[1024, BS], ldc=BS
            Ah = A3; B = B3; bias = bias3; Ch = Ch3;
            ldc = BS;
            int t = blockIdx.y * (1024 / NT) + blockIdx.x;   // 0..(2048*64/NT)
            rowA0 = (t & 7) * 128;
            colB0 = (t >> 3) * NT;
        }
    } else {
        Ah += z * strideA;
        B  += z * strideB;
    }

    float acc[4][NTL][4];
#pragma unroll
    for (int mt = 0; mt < 4; mt++)
#pragma unroll
        for (int nt = 0; nt < NTL; nt++)
#pragma unroll
            for (int r = 0; r < 4; r++) acc[mt][nt][r] = 0.f;

    const __half* gA = Ah + (size_t)rowA0 * lda;
    const __half* gB = B  + (size_t)colB0 * ldb;

    // one stage: A 128x64 fp16 (1024 chunks), B NTx64 fp16 (NT*8 chunks)
    auto issue_stage = [&](int kc, int stg) {
        const uint32_t sb = sbase + stg * STG_BYTES;
        const int k0 = kc * 64;
#pragma unroll
        for (int it = 0; it < 4; it++) {
            int idx = it * NTHR + tid;
            int r = idx >> 3, c = idx & 7;
            uint32_t so = swz(r, c);
            CP_ASYNC16(sb + so, gA + (size_t)r * lda + k0 + c * 8);
        }
#pragma unroll
        for (int it = 0; it < NT / 32; it++) {
            int idx = it * NTHR + tid;
            int r = idx >> 3, c = idx & 7;
            uint32_t so = swz(r, c);
            CP_ASYNC16(sb + B_OFF + so, gB + (size_t)r * ldb + k0 + c * 8);
        }
    };

    issue_stage(0, 0); CP_COMMIT();
    if (nchunk > 1) { issue_stage(1, 1); CP_COMMIT(); }

    const int a_row = lane & 15;
    const int a_csel = lane >> 4;
    const int b_row = (lane & 7) + ((lane >> 4) << 3);
    const int b_csel = (lane >> 3) & 1;

    int stg = 0;
    for (int kc = 0; kc < nchunk; kc++) {
        const int ahead = nchunk - 1 - kc;
        if (kc + 2 < nchunk) {
            issue_stage(kc + 2, (stg + 2) % 3);
            CP_COMMIT();
            CP_WAITN(2);
        } else if (ahead == 1) {
            CP_WAITN(1);
        } else {
            CP_WAITN(0);
        }
        __syncthreads();

        const uint32_t sb = sbase + stg * STG_BYTES;
        const uint32_t aA = sb, bB = sb + B_OFF;

#pragma unroll
        for (int ks = 0; ks < 4; ks++) {
            uint32_t fA[4][4], fB[NG][4];
            const int kchunk = ks * 2;

#pragma unroll
            for (int mt = 0; mt < 4; mt++)
                ldsm_x4(fA[mt], aA + swz(wm * 64 + mt * 16 + a_row, kchunk + a_csel));
#pragma unroll
            for (int g = 0; g < NG; g++)
                ldsm_x4(fB[g], bB + swz(wn * (NT / 4) + g * 16 + b_row, kchunk + b_csel));

#pragma unroll
            for (int mt = 0; mt < 4; mt++)
#pragma unroll
                for (int nt = 0; nt < NTL; nt++)
                    mma16816(acc[mt][nt], fA[mt], &fB[nt >> 1][(nt & 1) * 2]);
        }
        __syncthreads();
        stg = (stg + 1) % 3;
    }

    // ------------------------------ epilogue ------------------------------
    const int lrow = (lane >> 2);
    const int lcol = (lane & 3) * 2;

#pragma unroll
    for (int mt = 0; mt < 4; mt++) {
#pragma unroll
        for (int half = 0; half < 2; half++) {
            const int row = rowA0 + wm * 64 + mt * 16 + lrow + half * 8;
            float rb = 0.f;
            if (MODE == 5 && z == 2) rb = bias[row];
            float inv = 1.f;
            if (MODE == 4) inv = 1.f / rowsum[z * SEQ + row];

            float rsum = 0.f;   // MODE 3 partial row sum (this thread's cols)
#pragma unroll
            for (int nt = 0; nt < NTL; nt++) {
                const int col = colB0 + wn * (NT / 4) + nt * 8 + lcol;
                float v0 = acc[mt][nt][half * 2 + 0];
                float v1 = acc[mt][nt][half * 2 + 1];
                if (MODE == 3) {
                    v0 = __expf(v0);
                    v1 = __expf(v1);
                    rsum += v0 + v1;
                    *(uint32_t*)(Ch + z * strideC + (size_t)row * ldc + col) =
                        pack_half2(v0, v1);
                } else if (MODE == 4) {
                    float2 o = make_float2(v0 * inv, v1 * inv);
                    *(float2*)(Cf + z * strideC + (size_t)row * ldc + col) = o;
                } else {  // MODE 5
                    if (z == 2) { v0 += rb;  v1 += rb; }
                    else        { v0 = (v0 + bias[col]) * scale;
                                  v1 = (v1 + bias[col + 1]) * scale; }
                    *(uint32_t*)(Ch + (size_t)row * ldc + col) = pack_half2(v0, v1);
                }
            }
            if (MODE == 3) {
                // reduce over the 4 lanes covering this row (lane&3 varies)
                rsum += __shfl_xor_sync(0xFFFFFFFF, rsum, 1);
                rsum += __shfl_xor_sync(0xFFFFFFFF, rsum, 2);
                if ((lane & 3) == 0)
                    atomicAdd(&rowsum[z * SEQ + row], rsum);
            }
        }
    }
}

// ---------------------------------------------------------------------------
// fp32 -> fp16 round: x, and merged 3-weight variant
// ---------------------------------------------------------------------------
__global__ void __launch_bounds__(256, 8)
convert_kernel(const float* __restrict__ in, __half* __restrict__ out, size_t n)
{
    size_t i = ((size_t)blockIdx.x * blockDim.x + threadIdx.x) * 8;
    if (i >= n) return;
    float4 a = *(const float4*)(in + i);
    float4 b = *(const float4*)(in + i + 4);
    float v[8] = {a.x, a.y, a.z, a.w, b.x, b.y, b.z, b.w};
    alignas(16) uint32_t hw[4];
#pragma unroll
    for (int c = 0; c < 8; c += 2) hw[c >> 1] = pack_half2(v[c], v[c + 1]);
    *(uint4*)(out + i) = *(const uint4*)(&hw[0]);
}

__global__ void __launch_bounds__(256, 8)
convert3_kernel(const float* __restrict__ a, const float* __restrict__ b,
                const float* __restrict__ c,
                __half* __restrict__ oa, __half* __restrict__ ob,
                __half* __restrict__ oc, size_t n)
{
    const float* in;
    __half* out;
    if (blockIdx.y == 0)      { in = a; out = oa; }
    else if (blockIdx.y == 1) { in = b; out = ob; }
    else                      { in = c; out = oc; }
    size_t i = ((size_t)blockIdx.x * blockDim.x + threadIdx.x) * 8;
    if (i >= n) return;
    float4 p = *(const float4*)(in + i);
    float4 q = *(const float4*)(in + i + 4);
    float v[8] = {p.x, p.y, p.z, p.w, q.x, q.y, q.z, q.w};
    alignas(16) uint32_t hw[4];
#pragma unroll
    for (int cc = 0; cc < 8; cc += 2) hw[cc >> 1] = pack_half2(v[cc], v[cc + 1]);
    *(uint4*)(out + i) = *(const uint4*)(&hw[0]);
}

// zero the rowsum accumulator
__global__ void __launch_bounds__(256, 8)
zero_kernel(float* __restrict__ p, int n)
{
    int i = blockIdx.x * blockDim.x + threadIdx.x;
    if (i < n) p[i] = 0.f;
}

// ---------------------------------------------------------------------------
// Launch
// ---------------------------------------------------------------------------
#define SMEM_128 (NSTAGE * (16384 + 128 * 128))   // 98304
#define SMEM_64  (NSTAGE * (16384 + 64 * 128))    // 73728

extern "C" void kernel_launch(void* const* d_in, const int* in_sizes, int n_in,
                              void* d_out, int out_size)
{
    const float* x  = (const float*)d_in[0];
    const float* Wq = (const float*)d_in[1];
    const float* bq = (const float*)d_in[2];
    const float* Wk = (const float*)d_in[3];
    const float* bk = (const float*)d_in[4];
    const float* Wv = (const float*)d_in[5];
    const float* bv = (const float*)d_in[6];
    float* out = (float*)d_out;

    cudaFuncSetAttribute((const void*)gemm_tc<3, 128>, cudaFuncAttributeMaxDynamicSharedMemorySize, SMEM_128);
    cudaFuncSetAttribute((const void*)gemm_tc<4, 64>,  cudaFuncAttributeMaxDynamicSharedMemorySize, SMEM_64);
    cudaFuncSetAttribute((const void*)gemm_tc<5, 64>,  cudaFuncAttributeMaxDynamicSharedMemorySize, SMEM_64);

    __half *xh, *pWq, *pWk, *pWv, *Qh, *Kh, *Vth, *SP;
    float *rs;
    cudaGetSymbolAddress((void**)&xh, g_xh);
    cudaGetSymbolAddress((void**)&pWq, g_Wq);  cudaGetSymbolAddress((void**)&pWk, g_Wk);
    cudaGetSymbolAddress((void**)&pWv, g_Wv);
    cudaGetSymbolAddress((void**)&Qh, g_Qh);   cudaGetSymbolAddress((void**)&Kh, g_Kh);
    cudaGetSymbolAddress((void**)&Vth, g_Vth);
    cudaGetSymbolAddress((void**)&SP, g_SP);
    cudaGetSymbolAddress((void**)&rs, g_rowsum);

    const float qscale = 0.03125f;   // 1/sqrt(1024), exact power of two

    // 1) fp16 operands + zero rowsum
    convert_kernel<<<(size_t)BS * EMBED / 2048, 256>>>(x, xh, (size_t)BS * EMBED);
    {
        dim3 grid(EMBED * EMBED / 2048, 3);
        convert3_kernel<<<grid, 256>>>(Wq, Wk, Wv, pWq, pWk, pWv, (size_t)EMBED * EMBED);
    }
    zero_kernel<<<BS / 256, 256>>>(rs, BS);

    // 2) fused QKV, NT=64: z=0 Q, z=1 K, z=2 Vt (tile-remapped) — 6144 CTAs
    {
        dim3 grid(EMBED / 64, BS / 128, 3);    // (16, 128, 3)
        gemm_tc<5, 64><<<grid, NTHR, SMEM_64>>>(xh, pWq, bq, qscale,
                                                nullptr, Qh,
                                                EMBED, EMBED, EMBED, EMBED / 64, 0, 0, 0,
                                                pWk, bk, 1.0f, Kh,
                                                pWv, xh, bv, Vth,
                                                nullptr);
    }
    // 3) exp-scores = exp(Q K^T) -> fp16 SP + row-sum atomics, NT=128 (2048 CTAs)
    {
        dim3 grid(SEQ / 128, SEQ / 128, BATCH);
        gemm_tc<3, 128><<<grid, NTHR, SMEM_128>>>(Qh, Kh, nullptr, 1.0f,
                                                  nullptr, SP,
                                                  EMBED, EMBED, SEQ, EMBED / 64,
                                                  (long long)SEQ * EMBED,
                                                  (long long)SEQ * EMBED,
                                                  (long long)SEQ * SEQ,
                                                  nullptr, nullptr, 0.f, nullptr,
                                                  nullptr, nullptr, nullptr, nullptr,
                                                  rs);
    }
    // 4) out = (P' V) / rowsum, NT=64  (2048 CTAs)
    {
        dim3 grid(EMBED / 64, SEQ / 128, BATCH);   // (16, 16, 8)
        gemm_tc<4, 64><<<grid, NTHR, SMEM_64>>>(SP, Vth, nullptr, 1.0f,
                                                out, nullptr,
                                                SEQ, BS, EMBED, SEQ / 64,
                                                (long long)SEQ * SEQ,
                                                (long long)SEQ,
                                                (long long)SEQ * EMBED,
                                                nullptr, nullptr, 0.f, nullptr,
                                                nullptr, nullptr, nullptr, nullptr,
                                                rs);
    }
}

// round 17
// speedup vs baseline: 1.1661x; 1.1661x over previous
#include <cuda_runtime.h>
#include <cuda_fp16.h>
#include <cstdint>
#include <math.h>

#define BATCH 8
#define SEQ   2048
#define EMBED 1024
#define BS    (BATCH * SEQ)          // 16384

// ---------------------------------------------------------------------------
// Device-global scratch (allocation-free rule) — all fp16 operands
// ---------------------------------------------------------------------------
__device__ __half g_xh[(size_t)BS * EMBED];
__device__ __half g_Wq[EMBED * EMBED];
__device__ __half g_Wk[EMBED * EMBED];
__device__ __half g_Wv[EMBED * EMBED];
__device__ __half g_Qh[(size_t)BS * EMBED];
__device__ __half g_Kh[(size_t)BS * EMBED];
__device__ __half g_Vth[(size_t)EMBED * BS];        // V pre-transposed [EMBED][BS]
__device__ __half g_SP[(size_t)BATCH * SEQ * SEQ];  // exp(scores), unnormalized
__device__ float  g_rowsum[BS];                     // per-row sums of exp(scores)

// ---------------------------------------------------------------------------
// Helpers
// ---------------------------------------------------------------------------
__device__ __forceinline__ uint32_t smem_u32(const void* p) {
    uint32_t a;
    asm("{ .reg .u64 t; cvta.to.shared.u64 t, %1; cvt.u32.u64 %0, t; }" : "=r"(a) : "l"(p));
    return a;
}

#define CP_ASYNC16(sm, gp) \
    asm volatile("cp.async.cg.shared.global [%0], [%1], 16;" :: "r"(sm), "l"(gp) : "memory")
#define CP_COMMIT()  asm volatile("cp.async.commit_group;" ::: "memory")
#define CP_WAITN(n)  asm volatile("cp.async.wait_group %0;" :: "n"(n) : "memory")

__device__ __forceinline__ void ldsm_x4(uint32_t* r, uint32_t addr) {
    asm volatile("ldmatrix.sync.aligned.m8n8.x4.shared.b16 {%0,%1,%2,%3}, [%4];"
                 : "=r"(r[0]), "=r"(r[1]), "=r"(r[2]), "=r"(r[3]) : "r"(addr));
}

__device__ __forceinline__ void mma16816(float* c, const uint32_t* a, const uint32_t* b) {
    asm volatile(
        "mma.sync.aligned.m16n8k16.row.col.f32.f16.f16.f32 "
        "{%0,%1,%2,%3}, {%4,%5,%6,%7}, {%8,%9}, {%0,%1,%2,%3};"
        : "+f"(c[0]), "+f"(c[1]), "+f"(c[2]), "+f"(c[3])
        : "r"(a[0]), "r"(a[1]), "r"(a[2]), "r"(a[3]), "r"(b[0]), "r"(b[1]));
}

// byte offset of 16B chunk (row, c) inside a [rows][64 fp16] tile, xor-swizzled
__device__ __forceinline__ uint32_t swz(int row, int c) {
    return (uint32_t)((row * 8 + (c ^ (row & 7))) * 16);
}

__device__ __forceinline__ uint32_t pack_half2(float v0, float v1) {
    __half h0 = __float2half(v0), h1 = __float2half(v1);
    return (uint32_t)__half_as_ushort(h0) | ((uint32_t)__half_as_ushort(h1) << 16);
}

// ---------------------------------------------------------------------------
// HMMA GEMM NT: C[M,N] = A[M,K] * B[N,K]^T, fp16 in, fp32 accum.
// CTA tile 128x128, 256 threads = 8 warps (2x4), warp tile 64x32.
// K-chunk 64, 3-stage cp.async pipeline (32KB/stage), 2 CTAs/SM.
// MODE 3: v=exp(acc) -> fp16 Ch (z-strided) + per-row sum atomics -> rowsum
// MODE 4: v=acc * (1/rowsum[row]) -> fp32 Cf (z-strided)          [PV]
// MODE 5: fused QKV:
//   z=0: v=(acc+bq[col])*qscale -> Qh ; z=1: v=acc+bk[col] -> Kh
//   z=2: A=Wv, B=xh, tile remap, v=acc+bv[row] -> Vth (ldc=BS)
// ---------------------------------------------------------------------------
#define NSTAGE 3
#define STG_BYTES 32768
#define B_OFF 16384
#define GEMM_SMEM (NSTAGE * STG_BYTES)     // 98304 per CTA

template <int MODE>
__global__ void __launch_bounds__(256, 2)
gemm_tc(const __half* __restrict__ Ah,
        const __half* B, const float* bias, float scale,
        float* __restrict__ Cf, __half* Ch,
        int lda, int ldb, int ldc, int nchunk,
        long long strideA, long long strideB, long long strideC,
        const __half* B2, const float* bias2, float scale2, __half* Ch2,
        const __half* A3, const __half* B3, const float* bias3, __half* Ch3,
        float* __restrict__ rowsum)
{
    extern __shared__ char smem[];
    const uint32_t sbase = smem_u32(smem);
    const int tid = threadIdx.x;
    const int wid = tid >> 5;
    const int lane = tid & 31;
    const int wm = wid & 1;          // 0..1  M direction (64 rows each)
    const int wn = wid >> 1;         // 0..3  N direction (32 cols each)

    const long long z = blockIdx.z;
    int rowA0 = blockIdx.y * 128;
    int colB0 = blockIdx.x * 128;

    if (MODE == 5) {
        if (z == 1) { B = B2; bias = bias2; scale = scale2; Ch = Ch2; }
        else if (z == 2) {
            // Vt: A=Wv[1024,1024], B=xh[16384,1024], out Vth[1024, BS], ldc=BS
            Ah = A3; B = B3; bias = bias3; Ch = Ch3;
            ldc = BS;
            int t = blockIdx.y * 8 + blockIdx.x;     // 0..1023
            rowA0 = (t & 7) * 128;
            colB0 = (t >> 3) * 128;
        }
    } else {
        Ah += z * strideA;
        B  += z * strideB;
    }

    float acc[4][4][4];
#pragma unroll
    for (int mt = 0; mt < 4; mt++)
#pragma unroll
        for (int nt = 0; nt < 4; nt++)
#pragma unroll
            for (int r = 0; r < 4; r++) acc[mt][nt][r] = 0.f;

    const __half* gA = Ah + (size_t)rowA0 * lda;
    const __half* gB = B  + (size_t)colB0 * ldb;

    // one stage: A 128x64 fp16 (1024 chunks), B 128x64 fp16 (1024 chunks)
    auto issue_stage = [&](int kc, int stg) {
        const uint32_t sb = sbase + stg * STG_BYTES;
        const int k0 = kc * 64;
#pragma unroll
        for (int it = 0; it < 4; it++) {
            int idx = it * 256 + tid;
            int r = idx >> 3, c = idx & 7;
            uint32_t so = swz(r, c);
            CP_ASYNC16(sb + so, gA + (size_t)r * lda + k0 + c * 8);
        }
#pragma unroll
        for (int it = 0; it < 4; it++) {
            int idx = it * 256 + tid;
            int r = idx >> 3, c = idx & 7;
            uint32_t so = swz(r, c);
            CP_ASYNC16(sb + B_OFF + so, gB + (size_t)r * ldb + k0 + c * 8);
        }
    };

    issue_stage(0, 0); CP_COMMIT();
    if (nchunk > 1) { issue_stage(1, 1); CP_COMMIT(); }

    const int a_row = lane & 15;
    const int a_csel = lane >> 4;
    const int b_row = (lane & 7) + ((lane >> 4) << 3);
    const int b_csel = (lane >> 3) & 1;

    int stg = 0;
    for (int kc = 0; kc < nchunk; kc++) {
        const int ahead = nchunk - 1 - kc;
        if (kc + 2 < nchunk) {
            issue_stage(kc + 2, (stg + 2) % 3);
            CP_COMMIT();
            CP_WAITN(2);
        } else if (ahead == 1) {
            CP_WAITN(1);
        } else {
            CP_WAITN(0);
        }
        __syncthreads();

        const uint32_t sb = sbase + stg * STG_BYTES;
        const uint32_t aA = sb, bB = sb + B_OFF;

#pragma unroll
        for (int ks = 0; ks < 4; ks++) {
            uint32_t fA[4][4], fB[2][4];
            const int kchunk = ks * 2;

#pragma unroll
            for (int mt = 0; mt < 4; mt++)
                ldsm_x4(fA[mt], aA + swz(wm * 64 + mt * 16 + a_row, kchunk + a_csel));
#pragma unroll
            for (int g = 0; g < 2; g++)
                ldsm_x4(fB[g], bB + swz(wn * 32 + g * 16 + b_row, kchunk + b_csel));

#pragma unroll
            for (int mt = 0; mt < 4; mt++)
#pragma unroll
                for (int nt = 0; nt < 4; nt++)
                    mma16816(acc[mt][nt], fA[mt], &fB[nt >> 1][(nt & 1) * 2]);
        }
        __syncthreads();
        stg = (stg + 1) % 3;
    }

    // ------------------------------ epilogue ------------------------------
    const int lrow = (lane >> 2);
    const int lcol = (lane & 3) * 2;

#pragma unroll
    for (int mt = 0; mt < 4; mt++) {
#pragma unroll
        for (int half = 0; half < 2; half++) {
            const int row = rowA0 + wm * 64 + mt * 16 + lrow + half * 8;
            float rb = 0.f;
            if (MODE == 5 && z == 2) rb = bias[row];
            float inv = 1.f;
            if (MODE == 4) inv = 1.f / rowsum[z * SEQ + row];

            float rsum = 0.f;   // MODE 3 partial row sum (this thread's cols)
#pragma unroll
            for (int nt = 0; nt < 4; nt++) {
                const int col = colB0 + wn * 32 + nt * 8 + lcol;
                float v0 = acc[mt][nt][half * 2 + 0];
                float v1 = acc[mt][nt][half * 2 + 1];
                if (MODE == 3) {
                    v0 = __expf(v0);
                    v1 = __expf(v1);
                    rsum += v0 + v1;
                    *(uint32_t*)(Ch + z * strideC + (size_t)row * ldc + col) =
                        pack_half2(v0, v1);
                } else if (MODE == 4) {
                    float2 o = make_float2(v0 * inv, v1 * inv);
                    *(float2*)(Cf + z * strideC + (size_t)row * ldc + col) = o;
                } else {  // MODE 5
                    if (z == 2) { v0 += rb;  v1 += rb; }
                    else        { v0 = (v0 + bias[col]) * scale;
                                  v1 = (v1 + bias[col + 1]) * scale; }
                    *(uint32_t*)(Ch + (size_t)row * ldc + col) = pack_half2(v0, v1);
                }
            }
            if (MODE == 3) {
                // reduce over the 4 lanes covering this row (lane&3 varies)
                rsum += __shfl_xor_sync(0xFFFFFFFF, rsum, 1);
                rsum += __shfl_xor_sync(0xFFFFFFFF, rsum, 2);
                if ((lane & 3) == 0)
                    atomicAdd(&rowsum[z * SEQ + row], rsum);
            }
        }
    }
}

// ---------------------------------------------------------------------------
// fp32 -> fp16 round: x converter
// ---------------------------------------------------------------------------
__global__ void __launch_bounds__(256, 8)
convert_kernel(const float* __restrict__ in, __half* __restrict__ out, size_t n)
{
    size_t i = ((size_t)blockIdx.x * blockDim.x + threadIdx.x) * 8;
    if (i >= n) return;
    float4 a = *(const float4*)(in + i);
    float4 b = *(const float4*)(in + i + 4);
    float v[8] = {a.x, a.y, a.z, a.w, b.x, b.y, b.z, b.w};
    alignas(16) uint32_t hw[4];
#pragma unroll
    for (int c = 0; c < 8; c += 2) hw[c >> 1] = pack_half2(v[c], v[c + 1]);
    *(uint4*)(out + i) = *(const uint4*)(&hw[0]);
}

// merged 3-weight convert + rowsum zeroing (grid.y == 3)
__global__ void __launch_bounds__(256, 8)
convert3_kernel(const float* __restrict__ a, const float* __restrict__ b,
                const float* __restrict__ c,
                __half* __restrict__ oa, __half* __restrict__ ob,
                __half* __restrict__ oc, size_t n,
                float* __restrict__ rowsum, int nrs)
{
    if (blockIdx.y == 3) {
        int i = blockIdx.x * blockDim.x + threadIdx.x;
        if (i < nrs) rowsum[i] = 0.f;
        return;
    }
    const float* in;
    __half* out;
    if (blockIdx.y == 0)      { in = a; out = oa; }
    else if (blockIdx.y == 1) { in = b; out = ob; }
    else                      { in = c; out = oc; }
    size_t i = ((size_t)blockIdx.x * blockDim.x + threadIdx.x) * 8;
    if (i >= n) return;
    float4 p = *(const float4*)(in + i);
    float4 q = *(const float4*)(in + i + 4);
    float v[8] = {p.x, p.y, p.z, p.w, q.x, q.y, q.z, q.w};
    alignas(16) uint32_t hw[4];
#pragma unroll
    for (int cc = 0; cc < 8; cc += 2) hw[cc >> 1] = pack_half2(v[cc], v[cc + 1]);
    *(uint4*)(out + i) = *(const uint4*)(&hw[0]);
}

// ---------------------------------------------------------------------------
// Launch
// ---------------------------------------------------------------------------
extern "C" void kernel_launch(void* const* d_in, const int* in_sizes, int n_in,
                              void* d_out, int out_size)
{
    const float* x  = (const float*)d_in[0];
    const float* Wq = (const float*)d_in[1];
    const float* bq = (const float*)d_in[2];
    const float* Wk = (const float*)d_in[3];
    const float* bk = (const float*)d_in[4];
    const float* Wv = (const float*)d_in[5];
    const float* bv = (const float*)d_in[6];
    float* out = (float*)d_out;

    cudaFuncSetAttribute((const void*)gemm_tc<3>, cudaFuncAttributeMaxDynamicSharedMemorySize, GEMM_SMEM);
    cudaFuncSetAttribute((const void*)gemm_tc<4>, cudaFuncAttributeMaxDynamicSharedMemorySize, GEMM_SMEM);
    cudaFuncSetAttribute((const void*)gemm_tc<5>, cudaFuncAttributeMaxDynamicSharedMemorySize, GEMM_SMEM);

    __half *xh, *pWq, *pWk, *pWv, *Qh, *Kh, *Vth, *SP;
    float *rs;
    cudaGetSymbolAddress((void**)&xh, g_xh);
    cudaGetSymbolAddress((void**)&pWq, g_Wq);  cudaGetSymbolAddress((void**)&pWk, g_Wk);
    cudaGetSymbolAddress((void**)&pWv, g_Wv);
    cudaGetSymbolAddress((void**)&Qh, g_Qh);   cudaGetSymbolAddress((void**)&Kh, g_Kh);
    cudaGetSymbolAddress((void**)&Vth, g_Vth);
    cudaGetSymbolAddress((void**)&SP, g_SP);
    cudaGetSymbolAddress((void**)&rs, g_rowsum);

    const float qscale = 0.03125f;   // 1/sqrt(1024), exact power of two

    // 1) fp16 operands; weight converts + rowsum zero in one launch
    convert_kernel<<<(size_t)BS * EMBED / 2048, 256>>>(x, xh, (size_t)BS * EMBED);
    {
        dim3 grid(EMBED * EMBED / 2048, 4);   // y=0..2 weights, y=3 zeroes rowsum
        convert3_kernel<<<grid, 256>>>(Wq, Wk, Wv, pWq, pWk, pWv,
                                       (size_t)EMBED * EMBED, rs, BS);
    }

    // 2) fused QKV: z=0 Q, z=1 K, z=2 Vt (tile-remapped)  — 3072 CTAs
    {
        dim3 grid(EMBED / 128, BS / 128, 3);
        gemm_tc<5><<<grid, 256, GEMM_SMEM>>>(xh, pWq, bq, qscale,
                                             nullptr, Qh,
                                             EMBED, EMBED, EMBED, EMBED / 64, 0, 0, 0,
                                             pWk, bk, 1.0f, Kh,
                                             pWv, xh, bv, Vth,
                                             nullptr);
    }
    // 3) exp-scores = exp(Q K^T) -> fp16 SP + row-sum atomics  (2048 CTAs)
    {
        dim3 grid(SEQ / 128, SEQ / 128, BATCH);
        gemm_tc<3><<<grid, 256, GEMM_SMEM>>>(Qh, Kh, nullptr, 1.0f,
                                             nullptr, SP,
                                             EMBED, EMBED, SEQ, EMBED / 64,
                                             (long long)SEQ * EMBED,
                                             (long long)SEQ * EMBED,
                                             (long long)SEQ * SEQ,
                                             nullptr, nullptr, 0.f, nullptr,
                                             nullptr, nullptr, nullptr, nullptr,
                                             rs);
    }
    // 4) out = (P' V) / rowsum  (1024 CTAs)
    {
        dim3 grid(EMBED / 128, SEQ / 128, BATCH);
        gemm_tc<4><<<grid, 256, GEMM_SMEM>>>(SP, Vth, nullptr, 1.0f,
                                             out, nullptr,
                                             SEQ, BS, EMBED, SEQ / 64,
                                             (long long)SEQ * SEQ,
                                             (long long)SEQ,
                                             (long long)SEQ * EMBED,
                                             nullptr, nullptr, 0.f, nullptr,
                                             nullptr, nullptr, nullptr, nullptr,
                                             rs);
    }
}